// round 12
// baseline (speedup 1.0000x reference)
#include <cuda_runtime.h>
#include <cuda_bf16.h>
#include <stdint.h>

// ---------------- problem constants (fixed shapes) ----------------
#define BATCH 256
#define TT    250
#define CC    700
#define KP    704          // C padded (int8 bytes per row; 44*16)
#define KP16  352          // row length in uint16 units
#define H1    1024
#define H2    512
#define OO    20
#define BT    (BATCH*TT)   // 64000

// ---------------- device scratch ----------------
static __device__ uint8_t g_xd8[(size_t)BT * KP];         // delayed input {0,1} int8, 45MB
static __device__ int8_t  g_Wq[H1 * KP];                  // quantized W_in [h][c]
static __device__ float   g_qscale[H1];                   // per-row scales
static __device__ __nv_bfloat16 g_IinB[(size_t)BT * H1];  // I_in bf16 [r][h], 131MB
static __device__ float g_Wr1T[H1 * H1];                  // [j][h]
static __device__ float g_W2T[H1 * H2];                   // [j1][h2]
static __device__ float g_Wr2T[H2 * H2];                  // [j2][h2]
static __device__ float g_WoT[H2 * OO];                   // [j2][o]

#define CP_ASYNC16(dst_u32, src_ptr) \
    asm volatile("cp.async.cg.shared.global [%0], [%1], 16;\n" :: "r"(dst_u32), "l"(src_ptr))
#define CP_COMMIT() asm volatile("cp.async.commit_group;\n" ::)

// ---------------- K1: fused prep (R10-proven) ----------------
// blocks: [0,256) build_xd | [256,288) quant | [288,1312) Wr1T | [1312,1824) W2T |
//         [1824,2080) Wr2T | [2080] WoT
#define PB_TOTAL 2081

__global__ void __launch_bounds__(1024) k_prep_build(
    const float* __restrict__ x, const int* __restrict__ delays,
    const float* __restrict__ Win, const float* __restrict__ Wr1,
    const float* __restrict__ W2, const float* __restrict__ Wr2,
    const float* __restrict__ Wo)
{
    __shared__ uint8_t stage8[TT * 128];   // 32000 B
    __shared__ int dsh[KP];
    __shared__ float tile[32][33];

    const int blk = blockIdx.x;
    const int tid = threadIdx.x;
    const int tx = tid & 31, ty = tid >> 5;

    if (blk < 256) {
        const int b = blk;
        for (int i = tid; i < KP; i += 1024) dsh[i] = (i < CC) ? delays[i] : 0;

        const float* xb = x + (size_t)b * TT * CC;
        uint32_t* outw = reinterpret_cast<uint32_t*>(g_xd8) + (size_t)b * TT * (KP / 4);

        for (int c0 = 0; c0 < KP; c0 += 128) {
            const int w = (c0 + 128 <= CC) ? 128 : (CC > c0 ? CC - c0 : 0);   // 128 or 60
            __syncthreads();
            for (int idx = tid; idx < TT * 32; idx += 1024) {
                const int t = idx >> 5, c4 = idx & 31;
                uint32_t word = 0;
                if (c4 * 4 < w) {
                    const float4 v = *(const float4*)&xb[(size_t)t * CC + c0 + c4 * 4];
                    word  = (uint32_t)(v.x != 0.0f);
                    word |= (uint32_t)(v.y != 0.0f) << 8;
                    word |= (uint32_t)(v.z != 0.0f) << 16;
                    word |= (uint32_t)(v.w != 0.0f) << 24;
                }
                *reinterpret_cast<uint32_t*>(&stage8[t * 128 + c4 * 4]) = word;
            }
            __syncthreads();
            for (int idx = tid; idx < TT * 32; idx += 1024) {
                const int t = idx >> 5, w4 = idx & 31;
                uint32_t word = 0;
#pragma unroll
                for (int j = 0; j < 4; ++j) {
                    const int c = c0 + w4 * 4 + j;
                    const int ttt = t - dsh[c];
                    uint8_t byte = 0;
                    if (ttt >= 0 && (w4 * 4 + j) < w) byte = stage8[ttt * 128 + w4 * 4 + j];
                    word |= (uint32_t)byte << (8 * j);
                }
                outw[(size_t)t * (KP / 4) + (c0 >> 2) + w4] = word;
            }
        }
    } else if (blk < 288) {
        const int row = (blk - 256) * 32 + ty;
        float m = 0.0f;
        for (int c = tx; c < CC; c += 32) m = fmaxf(m, fabsf(Win[row * CC + c]));
#pragma unroll
        for (int off = 16; off; off >>= 1) m = fmaxf(m, __shfl_xor_sync(0xFFFFFFFFu, m, off));
        const float inv = (m > 0.0f) ? 127.0f / m : 0.0f;
        if (tx == 0) g_qscale[row] = m * (1.0f / 127.0f);
        for (int c = tx; c < KP; c += 32) {
            float wv = (c < CC) ? Win[row * CC + c] : 0.0f;
            g_Wq[row * KP + c] = (int8_t)__float2int_rn(wv * inv);
        }
    } else if (blk < 1312) {
        const int tI = blk - 288;
        const int tr = tI >> 5, tc = tI & 31;
        tile[ty][tx] = Wr1[(tr * 32 + ty) * H1 + tc * 32 + tx];
        __syncthreads();
        g_Wr1T[(tc * 32 + ty) * H1 + tr * 32 + tx] = tile[tx][ty];
    } else if (blk < 1824) {
        const int tI = blk - 1312;
        const int th = tI & 15, tj = tI >> 4;
        tile[ty][tx] = W2[(th * 32 + ty) * H1 + tj * 32 + tx];
        __syncthreads();
        g_W2T[(tj * 32 + ty) * H2 + th * 32 + tx] = tile[tx][ty];
    } else if (blk < 2080) {
        const int tI = blk - 1824;
        const int tr = tI >> 4, tc = tI & 15;
        tile[ty][tx] = Wr2[(tr * 32 + ty) * H2 + tc * 32 + tx];
        __syncthreads();
        g_Wr2T[(tc * 32 + ty) * H2 + tr * 32 + tx] = tile[tx][ty];
    } else {
        for (int i = tid; i < H2 * OO; i += 1024) {
            int j = i / OO, o = i % OO;
            g_WoT[i] = Wo[o * H2 + j];
        }
    }
}

// ---------------- K3: int8 IMMA GEMM, 4-stage cp.async (R9-proven) ----------------
#define BM 128
#define BN 128
#define BKK 32      // uint16 units per K-tile (= 64 int8)
#define SMSTR 40    // uint16 row stride (80B)
#define NSTG 4
#define GEMM_SMEM (NSTG * (BM + BN) * SMSTR * 2)   // 81920 bytes

#define CP_WAIT2()  asm volatile("cp.async.wait_group 2;\n" ::)

__global__ void __launch_bounds__(256, 2) k_gemm()
{
    extern __shared__ uint16_t smem[];
    uint16_t* Abase = smem;
    uint16_t* Bbase = smem + NSTG * BM * SMSTR;

    const int tid    = threadIdx.x;
    const int warpId = tid >> 5;
    const int lane   = tid & 31;
    const int g      = lane >> 2;
    const int t4     = lane & 3;

    const int row0 = blockIdx.y * BM;
    const int col0 = blockIdx.x * BN;
    const int wm   = (warpId & 1) * 64;
    const int wn   = (warpId >> 1) * 32;

    const int lrow0 = tid >> 2;
    const int lseg  = (tid & 3) * 8;   // uint16 units

    const uint16_t* Ag = reinterpret_cast<const uint16_t*>(g_xd8) + (size_t)row0 * KP16;
    const uint16_t* Bg = reinterpret_cast<const uint16_t*>(g_Wq)  + (size_t)col0 * KP16;

    uint32_t sA[NSTG], sB[NSTG];
#pragma unroll
    for (int s = 0; s < NSTG; ++s) {
        sA[s] = (uint32_t)__cvta_generic_to_shared(Abase + s * BM * SMSTR);
        sB[s] = (uint32_t)__cvta_generic_to_shared(Bbase + s * BN * SMSTR);
    }

    const int aoff = ((wm + (lane & 15)) * SMSTR + (lane >> 4) * 8) * 2;
    const int boff = ((wn + (lane & 7) + ((lane >> 4) << 3)) * SMSTR + ((lane >> 3) & 1) * 8) * 2;

    int acc[4][4][4];
#pragma unroll
    for (int i = 0; i < 4; ++i)
#pragma unroll
        for (int j = 0; j < 4; ++j)
#pragma unroll
            for (int c = 0; c < 4; ++c) acc[i][j][c] = 0;

    const int NK = KP16 / BKK;   // 11

#pragma unroll
    for (int s = 0; s < 3; ++s) {
        const int k0 = s * BKK;
        CP_ASYNC16(sA[s] + (lrow0 * SMSTR + lseg) * 2,        Ag + (size_t)lrow0 * KP16 + k0 + lseg);
        CP_ASYNC16(sA[s] + ((lrow0 + 64) * SMSTR + lseg) * 2, Ag + (size_t)(lrow0 + 64) * KP16 + k0 + lseg);
        CP_ASYNC16(sB[s] + (lrow0 * SMSTR + lseg) * 2,        Bg + (size_t)lrow0 * KP16 + k0 + lseg);
        CP_ASYNC16(sB[s] + ((lrow0 + 64) * SMSTR + lseg) * 2, Bg + (size_t)(lrow0 + 64) * KP16 + k0 + lseg);
        CP_COMMIT();
    }

    for (int kt = 0; kt < NK; ++kt) {
        const int st = kt & 3;
        CP_WAIT2();
        __syncthreads();

        if (kt + 3 < NK) {
            const int s = (kt + 3) & 3;
            const int k0 = (kt + 3) * BKK;
            CP_ASYNC16(sA[s] + (lrow0 * SMSTR + lseg) * 2,        Ag + (size_t)lrow0 * KP16 + k0 + lseg);
            CP_ASYNC16(sA[s] + ((lrow0 + 64) * SMSTR + lseg) * 2, Ag + (size_t)(lrow0 + 64) * KP16 + k0 + lseg);
            CP_ASYNC16(sB[s] + (lrow0 * SMSTR + lseg) * 2,        Bg + (size_t)lrow0 * KP16 + k0 + lseg);
            CP_ASYNC16(sB[s] + ((lrow0 + 64) * SMSTR + lseg) * 2, Bg + (size_t)(lrow0 + 64) * KP16 + k0 + lseg);
        }
        CP_COMMIT();

        const uint32_t aBase = sA[st] + aoff;
        const uint32_t bBase = sB[st] + boff;
#pragma unroll
        for (int ks = 0; ks < BKK; ks += 16) {
            uint32_t af[4][4];
            uint32_t bq[2][4];
#pragma unroll
            for (int i = 0; i < 4; ++i) {
                asm volatile("ldmatrix.sync.aligned.m8n8.x4.shared.b16 {%0,%1,%2,%3}, [%4];"
                             : "=r"(af[i][0]), "=r"(af[i][1]), "=r"(af[i][2]), "=r"(af[i][3])
                             : "r"(aBase + (i * 16 * SMSTR + ks) * 2));
            }
#pragma unroll
            for (int j2 = 0; j2 < 2; ++j2) {
                asm volatile("ldmatrix.sync.aligned.m8n8.x4.shared.b16 {%0,%1,%2,%3}, [%4];"
                             : "=r"(bq[j2][0]), "=r"(bq[j2][1]), "=r"(bq[j2][2]), "=r"(bq[j2][3])
                             : "r"(bBase + (j2 * 16 * SMSTR + ks) * 2));
            }
#pragma unroll
            for (int i = 0; i < 4; ++i)
#pragma unroll
                for (int j = 0; j < 4; ++j) {
                    const uint32_t b0 = bq[j >> 1][(j & 1) * 2];
                    const uint32_t b1 = bq[j >> 1][(j & 1) * 2 + 1];
                    asm volatile(
                        "mma.sync.aligned.m16n8k32.row.col.s32.s8.s8.s32 "
                        "{%0,%1,%2,%3}, {%4,%5,%6,%7}, {%8,%9}, {%0,%1,%2,%3};\n"
                        : "+r"(acc[i][j][0]), "+r"(acc[i][j][1]),
                          "+r"(acc[i][j][2]), "+r"(acc[i][j][3])
                        : "r"(af[i][0]), "r"(af[i][1]), "r"(af[i][2]), "r"(af[i][3]),
                          "r"(b0), "r"(b1));
                }
        }
    }

#pragma unroll
    for (int j = 0; j < 4; ++j) {
        const int c = col0 + wn + j * 8 + 2 * t4;
        const float sc0 = g_qscale[c];
        const float sc1 = g_qscale[c + 1];
#pragma unroll
        for (int i = 0; i < 4; ++i) {
            const int r0 = row0 + wm + i * 16 + g;
            __nv_bfloat162 p0 = __float22bfloat162_rn(
                make_float2(sc0 * (float)acc[i][j][0], sc1 * (float)acc[i][j][1]));
            __nv_bfloat162 p1 = __float22bfloat162_rn(
                make_float2(sc0 * (float)acc[i][j][2], sc1 * (float)acc[i][j][3]));
            *reinterpret_cast<__nv_bfloat162*>(&g_IinB[(size_t)r0 * H1 + c])       = p0;
            *reinterpret_cast<__nv_bfloat162*>(&g_IinB[(size_t)(r0 + 8) * H1 + c]) = p1;
        }
    }
}

// ---------------- K4: scan — ONE barrier/step via 4-slot list rotation ----------------
#define RSLOTS 8
#define RDEPTH 7

__global__ void __launch_bounds__(128) k_scan(
    const float* __restrict__ alpha1, const float* __restrict__ rho1, const float* __restrict__ beta_a1,
    const float* __restrict__ alpha2, const float* __restrict__ rho2, const float* __restrict__ beta_a2,
    const float* __restrict__ beta_out, float* __restrict__ out)
{
    __shared__ int cnt1[4], cnt2[4];
    __shared__ int act1[4][H1];
    __shared__ int act2[4][H2];
    __shared__ uint4 ring[RSLOTS][128];   // 16KB

    const int b   = blockIdx.x;
    const int tid = threadIdx.x;
    const int h0  = 8 * tid;
    const int h2  = 4 * tid;

    float alc1[8], rc1[8], bac1[8], v1[8], a1[8], s1[8];
#pragma unroll
    for (int k = 0; k < 2; ++k) {
        const float4 a = *(const float4*)&alpha1[h0 + 4 * k];
        const float4 r = *(const float4*)&rho1[h0 + 4 * k];
        const float4 bb = *(const float4*)&beta_a1[h0 + 4 * k];
        alc1[4*k] = a.x; alc1[4*k+1] = a.y; alc1[4*k+2] = a.z; alc1[4*k+3] = a.w;
        rc1[4*k] = r.x; rc1[4*k+1] = r.y; rc1[4*k+2] = r.z; rc1[4*k+3] = r.w;
        bac1[4*k] = bb.x; bac1[4*k+1] = bb.y; bac1[4*k+2] = bb.z; bac1[4*k+3] = bb.w;
    }
#pragma unroll
    for (int c = 0; c < 8; ++c) { v1[c] = 0.f; a1[c] = 0.f; s1[c] = 0.f; }

    float alc2[4], rc2[4], bac2[4], v2[4], a2[4], s2[4];
    {
        const float4 a = *(const float4*)&alpha2[h2];
        const float4 r = *(const float4*)&rho2[h2];
        const float4 bb = *(const float4*)&beta_a2[h2];
        alc2[0] = a.x; alc2[1] = a.y; alc2[2] = a.z; alc2[3] = a.w;
        rc2[0] = r.x; rc2[1] = r.y; rc2[2] = r.z; rc2[3] = r.w;
        bac2[0] = bb.x; bac2[1] = bb.y; bac2[2] = bb.z; bac2[3] = bb.w;
    }
#pragma unroll
    for (int c = 0; c < 4; ++c) { v2[c] = 0.f; a2[c] = 0.f; s2[c] = 0.f; }

    float bo = 0.f, obo = 0.f, vo = 0.f, vos = 0.f;
    if (tid < OO) { bo = beta_out[tid]; obo = 1.0f - bo; }

    if (tid == 0) {
#pragma unroll
        for (int s = 0; s < 4; ++s) { cnt1[s] = 0; cnt2[s] = 0; }
    }
    __syncthreads();

    const uint4* Ibg = reinterpret_cast<const uint4*>(g_IinB + (size_t)b * TT * H1) + tid;
    const uint32_t ringAddr = (uint32_t)__cvta_generic_to_shared(&ring[0][tid]);

#pragma unroll
    for (int s = 0; s < RDEPTH; ++s) {
        CP_ASYNC16(ringAddr + s * (128 * 16), Ibg + (size_t)s * (H1 / 8));
        CP_COMMIT();
    }

    for (int t = 0; t < TT; ++t) {
        asm volatile("cp.async.wait_group 6;\n" ::);
        const uint4 packed = ring[t & (RSLOTS - 1)][tid];
        {
            const int tn = t + RDEPTH;
            if (tn < TT)
                CP_ASYNC16(ringAddr + (tn & (RSLOTS - 1)) * (128 * 16), Ibg + (size_t)tn * (H1 / 8));
            CP_COMMIT();
        }

        const int sc = t & 3;            // current slot
        const int sp = (t + 3) & 3;      // previous step's slot ((t-1)&3)

        // ---- phase A: layer-1 update (reads act1[sp]) + publish act1[sc]
        float I1[8];
        {
            const uint32_t pw[4] = {packed.x, packed.y, packed.z, packed.w};
#pragma unroll
            for (int k = 0; k < 4; ++k) {
                const __nv_bfloat162 bp = *reinterpret_cast<const __nv_bfloat162*>(&pw[k]);
                I1[2*k]   = __low2float(bp);
                I1[2*k+1] = __high2float(bp);
            }
        }
        const int n1 = cnt1[sp];
        for (int i = 0; i < n1; ++i) {
            const float* wr = &g_Wr1T[act1[sp][i] * H1 + h0];
            const float4 w0 = *(const float4*)wr;
            const float4 w1 = *(const float4*)(wr + 4);
            I1[0] += w0.x; I1[1] += w0.y; I1[2] += w0.z; I1[3] += w0.w;
            I1[4] += w1.x; I1[5] += w1.y; I1[6] += w1.z; I1[7] += w1.w;
        }
        float ns1[8];
#pragma unroll
        for (int c = 0; c < 8; ++c) {
            v1[c] = alc1[c] * v1[c] + (1.0f - alc1[c]) * I1[c] - s1[c] - a1[c];
            ns1[c] = (v1[c] >= 1.0f) ? 1.0f : 0.0f;
            a1[c] = rc1[c] * a1[c] + bac1[c] * ns1[c];
            s1[c] = ns1[c];
        }
#pragma unroll
        for (int c = 0; c < 8; ++c)
            if (ns1[c] != 0.0f) { int idx = atomicAdd(&cnt1[sc], 1); act1[sc][idx] = h0 + c; }

        __syncthreads();                 // THE barrier

        // ---- phase C: layer-2 update (reads act1[sc], act2[sp]) + readout(t-1) + resets
        {
            float I2[4] = {0.f, 0.f, 0.f, 0.f};
            const int m1 = cnt1[sc];
            for (int i = 0; i < m1; ++i) {
                const float4 w = *(const float4*)&g_W2T[act1[sc][i] * H2 + h2];
                I2[0] += w.x; I2[1] += w.y; I2[2] += w.z; I2[3] += w.w;
            }
            const int n2 = cnt2[sp];
            for (int i = 0; i < n2; ++i) {
                const float4 w = *(const float4*)&g_Wr2T[act2[sp][i] * H2 + h2];
                I2[0] += w.x; I2[1] += w.y; I2[2] += w.z; I2[3] += w.w;
            }
            float ns2[4];
#pragma unroll
            for (int c = 0; c < 4; ++c) {
                v2[c] = alc2[c] * v2[c] + (1.0f - alc2[c]) * I2[c] - s2[c] - a2[c];
                ns2[c] = (v2[c] >= 1.0f) ? 1.0f : 0.0f;
                a2[c] = rc2[c] * a2[c] + bac2[c] * ns2[c];
                s2[c] = ns2[c];
            }
#pragma unroll
            for (int c = 0; c < 4; ++c)
                if (ns2[c] != 0.0f) { int idx = atomicAdd(&cnt2[sc], 1); act2[sc][idx] = h2 + c; }
        }
        // reset slot (t+2)&3 for reuse at step t+2 (last readers finished at C(t-1))
        if (tid == 0) cnt1[(t + 2) & 3] = 0;
        if (tid == 1) cnt2[(t + 2) & 3] = 0;

        if (tid < OO && t > 0) {
            // deferred readout for step t-1 (reads act2[sp], stable)
            float Io = 0.f;
            const int m2 = cnt2[sp];
            for (int i = 0; i < m2; ++i) Io += g_WoT[act2[sp][i] * OO + tid];
            vo = bo * vo + obo * Io;
            vos += vo;
        }
    }

    __syncthreads();   // final act2 list (slot 249&3 = 1) complete
    if (tid < OO) {
        float Io = 0.f;
        const int m2 = cnt2[249 & 3];
        for (int i = 0; i < m2; ++i) Io += g_WoT[act2[249 & 3][i] * OO + tid];
        vo = bo * vo + obo * Io;
        vos += vo;
        out[b * OO + tid] = vos * (1.0f / (float)TT);
    }
}

// ---------------- launch (serial, R10-proven structure) ----------------
extern "C" void kernel_launch(void* const* d_in, const int* in_sizes, int n_in,
                              void* d_out, int out_size)
{
    const float* x       = (const float*)d_in[0];
    const int*   delays  = (const int*)  d_in[1];
    const float* W_in    = (const float*)d_in[2];
    const float* W_rec1  = (const float*)d_in[3];
    const float* W2      = (const float*)d_in[4];
    const float* W_rec2  = (const float*)d_in[5];
    const float* W_out   = (const float*)d_in[6];
    const float* alpha1  = (const float*)d_in[7];
    const float* rho1    = (const float*)d_in[8];
    const float* beta_a1 = (const float*)d_in[9];
    const float* alpha2  = (const float*)d_in[10];
    const float* rho2    = (const float*)d_in[11];
    const float* beta_a2 = (const float*)d_in[12];
    const float* beta_out= (const float*)d_in[13];
    float* out = (float*)d_out;

    static int smem_set = 0;
    if (!smem_set) {
        cudaFuncSetAttribute(k_gemm, cudaFuncAttributeMaxDynamicSharedMemorySize, GEMM_SMEM);
        smem_set = 1;
    }

    k_prep_build<<<PB_TOTAL, 1024>>>(x, delays, W_in, W_rec1, W2, W_rec2, W_out);

    {
        dim3 grid(H1 / BN, BT / BM);   // (8, 500)
        k_gemm<<<grid, 256, GEMM_SMEM>>>();
    }

    k_scan<<<BATCH, 128>>>(alpha1, rho1, beta_a1, alpha2, rho2, beta_a2, beta_out, out);
}

// round 13
// speedup vs baseline: 1.1266x; 1.1266x over previous
#include <cuda_runtime.h>
#include <cuda_bf16.h>
#include <stdint.h>

// ---------------- problem constants (fixed shapes) ----------------
#define BATCH 256
#define TT    250
#define CC    700
#define KP    704          // C padded (int8 bytes per row; 44*16)
#define KP16  352          // row length in uint16 units
#define H1    1024
#define H2    512
#define OO    20
#define BT    (BATCH*TT)   // 64000

// ---------------- device scratch ----------------
static __device__ uint8_t g_xd8[(size_t)BT * KP];         // delayed input {0,1} int8, 45MB
static __device__ int8_t  g_Wq[H1 * KP];                  // quantized W_in [h][c]
static __device__ float   g_qscale[H1];                   // per-row scales
static __device__ __nv_bfloat16 g_IinB[(size_t)BT * H1];  // I_in bf16 [r][h], 131MB
static __device__ float g_Wr1T[H1 * H1];                  // [j][h]
static __device__ float g_W2T[H1 * H2];                   // [j1][h2]
static __device__ float g_Wr2T[H2 * H2];                  // [j2][h2]
static __device__ float g_WoT[H2 * OO];                   // [j2][o]
static __device__ int   g_uniflag;                        // 1 if neuron params uniform

#define CP_ASYNC16(dst_u32, src_ptr) \
    asm volatile("cp.async.cg.shared.global [%0], [%1], 16;\n" :: "r"(dst_u32), "l"(src_ptr))
#define CP_COMMIT() asm volatile("cp.async.commit_group;\n" ::)

// ---------------- K1: fused prep ----------------
// blocks: [0,256) build_xd | [256,288) quant | [288,1312) Wr1T | [1312,1824) W2T |
//         [1824,2080) Wr2T | [2080] WoT | [2081] uniformity check
#define PB_TOTAL 2082

__global__ void __launch_bounds__(1024) k_prep_build(
    const float* __restrict__ x, const int* __restrict__ delays,
    const float* __restrict__ Win, const float* __restrict__ Wr1,
    const float* __restrict__ W2, const float* __restrict__ Wr2,
    const float* __restrict__ Wo,
    const float* __restrict__ Al1, const float* __restrict__ Rh1, const float* __restrict__ Ba1,
    const float* __restrict__ Al2, const float* __restrict__ Rh2, const float* __restrict__ Ba2)
{
    __shared__ uint8_t stage8[TT * 128];   // 32000 B
    __shared__ int dsh[KP];
    __shared__ float tile[32][33];
    __shared__ int okflag;

    const int blk = blockIdx.x;
    const int tid = threadIdx.x;
    const int tx = tid & 31, ty = tid >> 5;

    if (blk < 256) {
        const int b = blk;
        for (int i = tid; i < KP; i += 1024) dsh[i] = (i < CC) ? delays[i] : 0;

        const float* xb = x + (size_t)b * TT * CC;
        uint32_t* outw = reinterpret_cast<uint32_t*>(g_xd8) + (size_t)b * TT * (KP / 4);

        for (int c0 = 0; c0 < KP; c0 += 128) {
            const int w = (c0 + 128 <= CC) ? 128 : (CC > c0 ? CC - c0 : 0);   // 128 or 60
            __syncthreads();
            for (int idx = tid; idx < TT * 32; idx += 1024) {
                const int t = idx >> 5, c4 = idx & 31;
                uint32_t word = 0;
                if (c4 * 4 < w) {
                    const float4 v = *(const float4*)&xb[(size_t)t * CC + c0 + c4 * 4];
                    word  = (uint32_t)(v.x != 0.0f);
                    word |= (uint32_t)(v.y != 0.0f) << 8;
                    word |= (uint32_t)(v.z != 0.0f) << 16;
                    word |= (uint32_t)(v.w != 0.0f) << 24;
                }
                *reinterpret_cast<uint32_t*>(&stage8[t * 128 + c4 * 4]) = word;
            }
            __syncthreads();
            for (int idx = tid; idx < TT * 32; idx += 1024) {
                const int t = idx >> 5, w4 = idx & 31;
                uint32_t word = 0;
#pragma unroll
                for (int j = 0; j < 4; ++j) {
                    const int c = c0 + w4 * 4 + j;
                    const int ttt = t - dsh[c];
                    uint8_t byte = 0;
                    if (ttt >= 0 && (w4 * 4 + j) < w) byte = stage8[ttt * 128 + w4 * 4 + j];
                    word |= (uint32_t)byte << (8 * j);
                }
                outw[(size_t)t * (KP / 4) + (c0 >> 2) + w4] = word;
            }
        }
    } else if (blk < 288) {
        const int row = (blk - 256) * 32 + ty;
        float m = 0.0f;
        for (int c = tx; c < CC; c += 32) m = fmaxf(m, fabsf(Win[row * CC + c]));
#pragma unroll
        for (int off = 16; off; off >>= 1) m = fmaxf(m, __shfl_xor_sync(0xFFFFFFFFu, m, off));
        const float inv = (m > 0.0f) ? 127.0f / m : 0.0f;
        if (tx == 0) g_qscale[row] = m * (1.0f / 127.0f);
        for (int c = tx; c < KP; c += 32) {
            float wv = (c < CC) ? Win[row * CC + c] : 0.0f;
            g_Wq[row * KP + c] = (int8_t)__float2int_rn(wv * inv);
        }
    } else if (blk < 1312) {
        const int tI = blk - 288;
        const int tr = tI >> 5, tc = tI & 31;
        tile[ty][tx] = Wr1[(tr * 32 + ty) * H1 + tc * 32 + tx];
        __syncthreads();
        g_Wr1T[(tc * 32 + ty) * H1 + tr * 32 + tx] = tile[tx][ty];
    } else if (blk < 1824) {
        const int tI = blk - 1312;
        const int th = tI & 15, tj = tI >> 4;
        tile[ty][tx] = W2[(th * 32 + ty) * H1 + tj * 32 + tx];
        __syncthreads();
        g_W2T[(tj * 32 + ty) * H2 + th * 32 + tx] = tile[tx][ty];
    } else if (blk < 2080) {
        const int tI = blk - 1824;
        const int tr = tI >> 4, tc = tI & 15;
        tile[ty][tx] = Wr2[(tr * 32 + ty) * H2 + tc * 32 + tx];
        __syncthreads();
        g_Wr2T[(tc * 32 + ty) * H2 + tr * 32 + tx] = tile[tx][ty];
    } else if (blk == 2080) {
        for (int i = tid; i < H2 * OO; i += 1024) {
            int j = i / OO, o = i % OO;
            g_WoT[i] = Wo[o * H2 + j];
        }
    } else {
        // uniformity check for fast-scan dispatch
        if (tid == 0) okflag = 1;
        __syncthreads();
        const float a10 = Al1[0], r10 = Rh1[0], b10 = Ba1[0];
        const float a20 = Al2[0], r20 = Rh2[0], b20 = Ba2[0];
        int good = 1;
        for (int i = tid; i < H1; i += 1024)
            if (Al1[i] != a10 || Rh1[i] != r10 || Ba1[i] != b10) good = 0;
        for (int i = tid; i < H2; i += 1024)
            if (Al2[i] != a20 || Rh2[i] != r20 || Ba2[i] != b20) good = 0;
        if (!good) atomicAnd(&okflag, 0);
        __syncthreads();
        if (tid == 0) g_uniflag = okflag;
    }
}

// ---------------- K3: int8 IMMA GEMM, 4-stage cp.async (R9-proven) ----------------
#define BM 128
#define BN 128
#define BKK 32      // uint16 units per K-tile (= 64 int8)
#define SMSTR 40    // uint16 row stride (80B)
#define NSTG 4
#define GEMM_SMEM (NSTG * (BM + BN) * SMSTR * 2)   // 81920 bytes

#define CP_WAIT2()  asm volatile("cp.async.wait_group 2;\n" ::: "memory")

__global__ void __launch_bounds__(256, 2) k_gemm()
{
    extern __shared__ uint16_t smem[];
    uint16_t* Abase = smem;
    uint16_t* Bbase = smem + NSTG * BM * SMSTR;

    const int tid    = threadIdx.x;
    const int warpId = tid >> 5;
    const int lane   = tid & 31;
    const int g      = lane >> 2;
    const int t4     = lane & 3;

    const int row0 = blockIdx.y * BM;
    const int col0 = blockIdx.x * BN;
    const int wm   = (warpId & 1) * 64;
    const int wn   = (warpId >> 1) * 32;

    const int lrow0 = tid >> 2;
    const int lseg  = (tid & 3) * 8;   // uint16 units

    const uint16_t* Ag = reinterpret_cast<const uint16_t*>(g_xd8) + (size_t)row0 * KP16;
    const uint16_t* Bg = reinterpret_cast<const uint16_t*>(g_Wq)  + (size_t)col0 * KP16;

    uint32_t sA[NSTG], sB[NSTG];
#pragma unroll
    for (int s = 0; s < NSTG; ++s) {
        sA[s] = (uint32_t)__cvta_generic_to_shared(Abase + s * BM * SMSTR);
        sB[s] = (uint32_t)__cvta_generic_to_shared(Bbase + s * BN * SMSTR);
    }

    const int aoff = ((wm + (lane & 15)) * SMSTR + (lane >> 4) * 8) * 2;
    const int boff = ((wn + (lane & 7) + ((lane >> 4) << 3)) * SMSTR + ((lane >> 3) & 1) * 8) * 2;

    int acc[4][4][4];
#pragma unroll
    for (int i = 0; i < 4; ++i)
#pragma unroll
        for (int j = 0; j < 4; ++j)
#pragma unroll
            for (int c = 0; c < 4; ++c) acc[i][j][c] = 0;

    const int NK = KP16 / BKK;   // 11

#pragma unroll
    for (int s = 0; s < 3; ++s) {
        const int k0 = s * BKK;
        CP_ASYNC16(sA[s] + (lrow0 * SMSTR + lseg) * 2,        Ag + (size_t)lrow0 * KP16 + k0 + lseg);
        CP_ASYNC16(sA[s] + ((lrow0 + 64) * SMSTR + lseg) * 2, Ag + (size_t)(lrow0 + 64) * KP16 + k0 + lseg);
        CP_ASYNC16(sB[s] + (lrow0 * SMSTR + lseg) * 2,        Bg + (size_t)lrow0 * KP16 + k0 + lseg);
        CP_ASYNC16(sB[s] + ((lrow0 + 64) * SMSTR + lseg) * 2, Bg + (size_t)(lrow0 + 64) * KP16 + k0 + lseg);
        CP_COMMIT();
    }

    for (int kt = 0; kt < NK; ++kt) {
        const int st = kt & 3;
        CP_WAIT2();
        __syncthreads();

        if (kt + 3 < NK) {
            const int s = (kt + 3) & 3;
            const int k0 = (kt + 3) * BKK;
            CP_ASYNC16(sA[s] + (lrow0 * SMSTR + lseg) * 2,        Ag + (size_t)lrow0 * KP16 + k0 + lseg);
            CP_ASYNC16(sA[s] + ((lrow0 + 64) * SMSTR + lseg) * 2, Ag + (size_t)(lrow0 + 64) * KP16 + k0 + lseg);
            CP_ASYNC16(sB[s] + (lrow0 * SMSTR + lseg) * 2,        Bg + (size_t)lrow0 * KP16 + k0 + lseg);
            CP_ASYNC16(sB[s] + ((lrow0 + 64) * SMSTR + lseg) * 2, Bg + (size_t)(lrow0 + 64) * KP16 + k0 + lseg);
        }
        CP_COMMIT();

        const uint32_t aBase = sA[st] + aoff;
        const uint32_t bBase = sB[st] + boff;
#pragma unroll
        for (int ks = 0; ks < BKK; ks += 16) {
            uint32_t af[4][4];
            uint32_t bq[2][4];
#pragma unroll
            for (int i = 0; i < 4; ++i) {
                asm volatile("ldmatrix.sync.aligned.m8n8.x4.shared.b16 {%0,%1,%2,%3}, [%4];"
                             : "=r"(af[i][0]), "=r"(af[i][1]), "=r"(af[i][2]), "=r"(af[i][3])
                             : "r"(aBase + (i * 16 * SMSTR + ks) * 2));
            }
#pragma unroll
            for (int j2 = 0; j2 < 2; ++j2) {
                asm volatile("ldmatrix.sync.aligned.m8n8.x4.shared.b16 {%0,%1,%2,%3}, [%4];"
                             : "=r"(bq[j2][0]), "=r"(bq[j2][1]), "=r"(bq[j2][2]), "=r"(bq[j2][3])
                             : "r"(bBase + (j2 * 16 * SMSTR + ks) * 2));
            }
#pragma unroll
            for (int i = 0; i < 4; ++i)
#pragma unroll
                for (int j = 0; j < 4; ++j) {
                    const uint32_t b0 = bq[j >> 1][(j & 1) * 2];
                    const uint32_t b1 = bq[j >> 1][(j & 1) * 2 + 1];
                    asm volatile(
                        "mma.sync.aligned.m16n8k32.row.col.s32.s8.s8.s32 "
                        "{%0,%1,%2,%3}, {%4,%5,%6,%7}, {%8,%9}, {%0,%1,%2,%3};\n"
                        : "+r"(acc[i][j][0]), "+r"(acc[i][j][1]),
                          "+r"(acc[i][j][2]), "+r"(acc[i][j][3])
                        : "r"(af[i][0]), "r"(af[i][1]), "r"(af[i][2]), "r"(af[i][3]),
                          "r"(b0), "r"(b1));
                }
        }
    }

#pragma unroll
    for (int j = 0; j < 4; ++j) {
        const int c = col0 + wn + j * 8 + 2 * t4;
        const float sc0 = g_qscale[c];
        const float sc1 = g_qscale[c + 1];
#pragma unroll
        for (int i = 0; i < 4; ++i) {
            const int r0 = row0 + wm + i * 16 + g;
            __nv_bfloat162 p0 = __float22bfloat162_rn(
                make_float2(sc0 * (float)acc[i][j][0], sc1 * (float)acc[i][j][1]));
            __nv_bfloat162 p1 = __float22bfloat162_rn(
                make_float2(sc0 * (float)acc[i][j][2], sc1 * (float)acc[i][j][3]));
            *reinterpret_cast<__nv_bfloat162*>(&g_IinB[(size_t)r0 * H1 + c])       = p0;
            *reinterpret_cast<__nv_bfloat162*>(&g_IinB[(size_t)(r0 + 8) * H1 + c]) = p1;
        }
    }
}

// ---------------- K4a: FAST scan — one warp per batch, no barriers ----------------
// Requires uniform alpha/rho/beta (checked in prep -> g_uniflag).
// Lane owns L1 neurons {256g+8*lane+j : g<4, j<8} (mask bit g*8+j) and
// L2 neurons {256g+8*lane+j : g<2, j<8} (mask bit g*8+j).
__global__ void __launch_bounds__(128) k_scan_fast(
    const float* __restrict__ alpha1, const float* __restrict__ rho1, const float* __restrict__ beta_a1,
    const float* __restrict__ alpha2, const float* __restrict__ rho2, const float* __restrict__ beta_a2,
    const float* __restrict__ beta_out, float* __restrict__ out)
{
    if (!g_uniflag) return;

    __shared__ uint4 ring[4][4][128];   // [warp][slot][chunk] = 32KB

    const int wid  = threadIdx.x >> 5;
    const int lane = threadIdx.x & 31;
    const int b    = blockIdx.x * 4 + wid;

    const float al1 = alpha1[0], om1 = 1.0f - al1, rh1 = rho1[0], bA1 = beta_a1[0];
    const float al2 = alpha2[0], om2 = 1.0f - al2, rh2 = rho2[0], bA2 = beta_a2[0];
    float bo = 0.f, obo = 0.f;
    if (lane < OO) { bo = beta_out[lane]; obo = 1.0f - bo; }

    float v1[32], a1[32], v2[16], a2[16];
#pragma unroll
    for (int n = 0; n < 32; ++n) { v1[n] = 0.f; a1[n] = 0.f; }
#pragma unroll
    for (int n = 0; n < 16; ++n) { v2[n] = 0.f; a2[n] = 0.f; }
    uint32_t m1 = 0, m2 = 0;
    bool fA1 = false, fA2 = false;
    float vo = 0.f, vos = 0.f;

    const uint4* Ibg = reinterpret_cast<const uint4*>(g_IinB + (size_t)b * TT * H1);
    uint32_t rA[4];
#pragma unroll
    for (int g = 0; g < 4; ++g)
        rA[g] = (uint32_t)__cvta_generic_to_shared(&ring[wid][0][lane + 32 * g]);

#pragma unroll
    for (int s = 0; s < 3; ++s) {
#pragma unroll
        for (int g = 0; g < 4; ++g)
            CP_ASYNC16(rA[g] + s * 2048, Ibg + (size_t)s * 128 + lane + 32 * g);
        CP_COMMIT();
    }

    for (int t = 0; t < TT; ++t) {
        asm volatile("cp.async.wait_group 2;\n" ::: "memory");
        const int sl = t & 3;
        uint4 c[4];
#pragma unroll
        for (int g = 0; g < 4; ++g) c[g] = ring[wid][sl][lane + 32 * g];
        {
            const int tn = t + 3;
            if (tn < TT) {
#pragma unroll
                for (int g = 0; g < 4; ++g)
                    CP_ASYNC16(rA[g] + (tn & 3) * 2048, Ibg + (size_t)tn * 128 + lane + 32 * g);
            }
            CP_COMMIT();
        }

        float I1[32];
#pragma unroll
        for (int g = 0; g < 4; ++g) {
            const uint32_t wds[4] = {c[g].x, c[g].y, c[g].z, c[g].w};
#pragma unroll
            for (int q = 0; q < 4; ++q) {
                const float2 f = __bfloat1622float2(
                    *reinterpret_cast<const __nv_bfloat162*>(&wds[q]));
                I1[g * 8 + 2 * q]     = f.x;
                I1[g * 8 + 2 * q + 1] = f.y;
            }
        }

        // ---- recurrent L1 input from prev-step spikes
        uint32_t act = __ballot_sync(0xFFFFFFFFu, m1 != 0);
        const bool fS1 = (act != 0);
        while (act) {
            const int l = __ffs(act) - 1; act &= act - 1;
            uint32_t mm = __shfl_sync(0xFFFFFFFFu, m1, l);
            while (mm) {
                const int k = __ffs(mm) - 1; mm &= mm - 1;
                const int n = 256 * (k >> 3) + 8 * l + (k & 7);
                const float* wr = &g_Wr1T[(size_t)n * H1];
#pragma unroll
                for (int g = 0; g < 4; ++g) {
                    const float4 w0 = *(const float4*)&wr[g * 256 + 8 * lane];
                    const float4 w1 = *(const float4*)&wr[g * 256 + 8 * lane + 4];
                    I1[g*8+0] += w0.x; I1[g*8+1] += w0.y; I1[g*8+2] += w0.z; I1[g*8+3] += w0.w;
                    I1[g*8+4] += w1.x; I1[g*8+5] += w1.y; I1[g*8+6] += w1.z; I1[g*8+7] += w1.w;
                }
            }
        }

        // ---- layer-1 membrane update
        if (!fS1 && !fA1) {
#pragma unroll
            for (int n = 0; n < 32; ++n) v1[n] = fmaf(al1, v1[n], om1 * I1[n]);
        } else {
#pragma unroll
            for (int n = 0; n < 32; ++n) {
                const float s = (float)((m1 >> n) & 1u);
                v1[n] = fmaf(al1, v1[n], om1 * I1[n]) - s - a1[n];
            }
        }
        float mx = v1[0];
#pragma unroll
        for (int n = 1; n < 32; ++n) mx = fmaxf(mx, v1[n]);
        uint32_t nm1 = 0;
        if (__any_sync(0xFFFFFFFFu, mx >= 1.0f)) {
#pragma unroll
            for (int n = 0; n < 32; ++n) {
                const bool sp = (v1[n] >= 1.0f);
                nm1 |= ((uint32_t)sp) << n;
                a1[n] = rh1 * a1[n] + (sp ? bA1 : 0.0f);
            }
            fA1 = true;
        } else if (fA1) {
#pragma unroll
            for (int n = 0; n < 32; ++n) a1[n] = rh1 * a1[n];
        }

        // ---- layer-2 input: this step's L1 spikes + prev L2 spikes
        float I2[16];
#pragma unroll
        for (int n = 0; n < 16; ++n) I2[n] = 0.f;
        uint32_t act1n = __ballot_sync(0xFFFFFFFFu, nm1 != 0);
        const bool fI2 = (act1n != 0);
        while (act1n) {
            const int l = __ffs(act1n) - 1; act1n &= act1n - 1;
            uint32_t mm = __shfl_sync(0xFFFFFFFFu, nm1, l);
            while (mm) {
                const int k = __ffs(mm) - 1; mm &= mm - 1;
                const int n = 256 * (k >> 3) + 8 * l + (k & 7);
                const float* wr = &g_W2T[(size_t)n * H2];
#pragma unroll
                for (int g = 0; g < 2; ++g) {
                    const float4 w0 = *(const float4*)&wr[g * 256 + 8 * lane];
                    const float4 w1 = *(const float4*)&wr[g * 256 + 8 * lane + 4];
                    I2[g*8+0] += w0.x; I2[g*8+1] += w0.y; I2[g*8+2] += w0.z; I2[g*8+3] += w0.w;
                    I2[g*8+4] += w1.x; I2[g*8+5] += w1.y; I2[g*8+6] += w1.z; I2[g*8+7] += w1.w;
                }
            }
        }
        uint32_t act2p = __ballot_sync(0xFFFFFFFFu, m2 != 0);
        const bool fS2 = (act2p != 0);
        while (act2p) {
            const int l = __ffs(act2p) - 1; act2p &= act2p - 1;
            uint32_t mm = __shfl_sync(0xFFFFFFFFu, m2, l);
            while (mm) {
                const int k = __ffs(mm) - 1; mm &= mm - 1;
                const int n = 256 * (k >> 3) + 8 * l + (k & 7);
                const float* wr = &g_Wr2T[(size_t)n * H2];
#pragma unroll
                for (int g = 0; g < 2; ++g) {
                    const float4 w0 = *(const float4*)&wr[g * 256 + 8 * lane];
                    const float4 w1 = *(const float4*)&wr[g * 256 + 8 * lane + 4];
                    I2[g*8+0] += w0.x; I2[g*8+1] += w0.y; I2[g*8+2] += w0.z; I2[g*8+3] += w0.w;
                    I2[g*8+4] += w1.x; I2[g*8+5] += w1.y; I2[g*8+6] += w1.z; I2[g*8+7] += w1.w;
                }
            }
        }

        // ---- layer-2 membrane update
        if (!fI2 && !fS2 && !fA2) {
#pragma unroll
            for (int n = 0; n < 16; ++n) v2[n] = al2 * v2[n];
        } else {
#pragma unroll
            for (int n = 0; n < 16; ++n) {
                const float s = (float)((m2 >> n) & 1u);
                v2[n] = fmaf(al2, v2[n], om2 * I2[n]) - s - a2[n];
            }
        }
        float mx2 = v2[0];
#pragma unroll
        for (int n = 1; n < 16; ++n) mx2 = fmaxf(mx2, v2[n]);
        uint32_t nm2 = 0;
        if (__any_sync(0xFFFFFFFFu, mx2 >= 1.0f)) {
#pragma unroll
            for (int n = 0; n < 16; ++n) {
                const bool sp = (v2[n] >= 1.0f);
                nm2 |= ((uint32_t)sp) << n;
                a2[n] = rh2 * a2[n] + (sp ? bA2 : 0.0f);
            }
            fA2 = true;
        } else if (fA2) {
#pragma unroll
            for (int n = 0; n < 16; ++n) a2[n] = rh2 * a2[n];
        }

        // ---- readout (this step's L2 spikes)
        float Io = 0.f;
        uint32_t act2n = __ballot_sync(0xFFFFFFFFu, nm2 != 0);
        while (act2n) {
            const int l = __ffs(act2n) - 1; act2n &= act2n - 1;
            uint32_t mm = __shfl_sync(0xFFFFFFFFu, nm2, l);
            while (mm) {
                const int k = __ffs(mm) - 1; mm &= mm - 1;
                const int n = 256 * (k >> 3) + 8 * l + (k & 7);
                if (lane < OO) Io += g_WoT[n * OO + lane];
            }
        }
        vo = bo * vo + obo * Io;
        vos += vo;

        m1 = nm1; m2 = nm2;
    }

    if (lane < OO) out[b * OO + lane] = vos * (1.0f / (float)TT);
}

// ---------------- K4b: GENERAL fallback scan (R12-proven; runs only if non-uniform) ----
#define RSLOTS 8
#define RDEPTH 7

__global__ void __launch_bounds__(128) k_scan(
    const float* __restrict__ alpha1, const float* __restrict__ rho1, const float* __restrict__ beta_a1,
    const float* __restrict__ alpha2, const float* __restrict__ rho2, const float* __restrict__ beta_a2,
    const float* __restrict__ beta_out, float* __restrict__ out)
{
    if (g_uniflag) return;   // fast kernel already handled it

    __shared__ int cnt1[4], cnt2[4];
    __shared__ int act1[4][H1];
    __shared__ int act2[4][H2];
    __shared__ uint4 ring[RSLOTS][128];

    const int b   = blockIdx.x;
    const int tid = threadIdx.x;
    const int h0  = 8 * tid;
    const int h2  = 4 * tid;

    float alc1[8], rc1[8], bac1[8], v1[8], a1[8], s1[8];
#pragma unroll
    for (int k = 0; k < 2; ++k) {
        const float4 a = *(const float4*)&alpha1[h0 + 4 * k];
        const float4 r = *(const float4*)&rho1[h0 + 4 * k];
        const float4 bb = *(const float4*)&beta_a1[h0 + 4 * k];
        alc1[4*k] = a.x; alc1[4*k+1] = a.y; alc1[4*k+2] = a.z; alc1[4*k+3] = a.w;
        rc1[4*k] = r.x; rc1[4*k+1] = r.y; rc1[4*k+2] = r.z; rc1[4*k+3] = r.w;
        bac1[4*k] = bb.x; bac1[4*k+1] = bb.y; bac1[4*k+2] = bb.z; bac1[4*k+3] = bb.w;
    }
#pragma unroll
    for (int c = 0; c < 8; ++c) { v1[c] = 0.f; a1[c] = 0.f; s1[c] = 0.f; }

    float alc2[4], rc2[4], bac2[4], v2[4], a2[4], s2[4];
    {
        const float4 a = *(const float4*)&alpha2[h2];
        const float4 r = *(const float4*)&rho2[h2];
        const float4 bb = *(const float4*)&beta_a2[h2];
        alc2[0] = a.x; alc2[1] = a.y; alc2[2] = a.z; alc2[3] = a.w;
        rc2[0] = r.x; rc2[1] = r.y; rc2[2] = r.z; rc2[3] = r.w;
        bac2[0] = bb.x; bac2[1] = bb.y; bac2[2] = bb.z; bac2[3] = bb.w;
    }
#pragma unroll
    for (int c = 0; c < 4; ++c) { v2[c] = 0.f; a2[c] = 0.f; s2[c] = 0.f; }

    float bo = 0.f, obo = 0.f, vo = 0.f, vos = 0.f;
    if (tid < OO) { bo = beta_out[tid]; obo = 1.0f - bo; }

    if (tid == 0) {
#pragma unroll
        for (int s = 0; s < 4; ++s) { cnt1[s] = 0; cnt2[s] = 0; }
    }
    __syncthreads();

    const uint4* Ibg = reinterpret_cast<const uint4*>(g_IinB + (size_t)b * TT * H1) + tid;
    const uint32_t ringAddr = (uint32_t)__cvta_generic_to_shared(&ring[0][tid]);

#pragma unroll
    for (int s = 0; s < RDEPTH; ++s) {
        CP_ASYNC16(ringAddr + s * (128 * 16), Ibg + (size_t)s * (H1 / 8));
        CP_COMMIT();
    }

    for (int t = 0; t < TT; ++t) {
        asm volatile("cp.async.wait_group 6;\n" ::: "memory");
        const uint4 packed = ring[t & (RSLOTS - 1)][tid];
        {
            const int tn = t + RDEPTH;
            if (tn < TT)
                CP_ASYNC16(ringAddr + (tn & (RSLOTS - 1)) * (128 * 16), Ibg + (size_t)tn * (H1 / 8));
            CP_COMMIT();
        }

        const int sc = t & 3;
        const int sp = (t + 3) & 3;

        float I1[8];
        {
            const uint32_t pw[4] = {packed.x, packed.y, packed.z, packed.w};
#pragma unroll
            for (int k = 0; k < 4; ++k) {
                const __nv_bfloat162 bp = *reinterpret_cast<const __nv_bfloat162*>(&pw[k]);
                I1[2*k]   = __low2float(bp);
                I1[2*k+1] = __high2float(bp);
            }
        }
        const int n1 = cnt1[sp];
        for (int i = 0; i < n1; ++i) {
            const float* wr = &g_Wr1T[act1[sp][i] * H1 + h0];
            const float4 w0 = *(const float4*)wr;
            const float4 w1 = *(const float4*)(wr + 4);
            I1[0] += w0.x; I1[1] += w0.y; I1[2] += w0.z; I1[3] += w0.w;
            I1[4] += w1.x; I1[5] += w1.y; I1[6] += w1.z; I1[7] += w1.w;
        }
        float ns1[8];
#pragma unroll
        for (int c = 0; c < 8; ++c) {
            v1[c] = alc1[c] * v1[c] + (1.0f - alc1[c]) * I1[c] - s1[c] - a1[c];
            ns1[c] = (v1[c] >= 1.0f) ? 1.0f : 0.0f;
            a1[c] = rc1[c] * a1[c] + bac1[c] * ns1[c];
            s1[c] = ns1[c];
        }
#pragma unroll
        for (int c = 0; c < 8; ++c)
            if (ns1[c] != 0.0f) { int idx = atomicAdd(&cnt1[sc], 1); act1[sc][idx] = h0 + c; }

        __syncthreads();

        {
            float I2[4] = {0.f, 0.f, 0.f, 0.f};
            const int m1c = cnt1[sc];
            for (int i = 0; i < m1c; ++i) {
                const float4 w = *(const float4*)&g_W2T[act1[sc][i] * H2 + h2];
                I2[0] += w.x; I2[1] += w.y; I2[2] += w.z; I2[3] += w.w;
            }
            const int n2 = cnt2[sp];
            for (int i = 0; i < n2; ++i) {
                const float4 w = *(const float4*)&g_Wr2T[act2[sp][i] * H2 + h2];
                I2[0] += w.x; I2[1] += w.y; I2[2] += w.z; I2[3] += w.w;
            }
            float ns2[4];
#pragma unroll
            for (int c = 0; c < 4; ++c) {
                v2[c] = alc2[c] * v2[c] + (1.0f - alc2[c]) * I2[c] - s2[c] - a2[c];
                ns2[c] = (v2[c] >= 1.0f) ? 1.0f : 0.0f;
                a2[c] = rc2[c] * a2[c] + bac2[c] * ns2[c];
                s2[c] = ns2[c];
            }
#pragma unroll
            for (int c = 0; c < 4; ++c)
                if (ns2[c] != 0.0f) { int idx = atomicAdd(&cnt2[sc], 1); act2[sc][idx] = h2 + c; }
        }
        if (tid == 0) cnt1[(t + 2) & 3] = 0;
        if (tid == 1) cnt2[(t + 2) & 3] = 0;

        if (tid < OO && t > 0) {
            float Io = 0.f;
            const int m2c = cnt2[sp];
            for (int i = 0; i < m2c; ++i) Io += g_WoT[act2[sp][i] * OO + tid];
            vo = bo * vo + obo * Io;
            vos += vo;
        }
    }

    __syncthreads();
    if (tid < OO) {
        float Io = 0.f;
        const int m2c = cnt2[249 & 3];
        for (int i = 0; i < m2c; ++i) Io += g_WoT[act2[249 & 3][i] * OO + tid];
        vo = bo * vo + obo * Io;
        vos += vo;
        out[b * OO + tid] = vos * (1.0f / (float)TT);
    }
}

// ---------------- launch ----------------
extern "C" void kernel_launch(void* const* d_in, const int* in_sizes, int n_in,
                              void* d_out, int out_size)
{
    const float* x       = (const float*)d_in[0];
    const int*   delays  = (const int*)  d_in[1];
    const float* W_in    = (const float*)d_in[2];
    const float* W_rec1  = (const float*)d_in[3];
    const float* W2      = (const float*)d_in[4];
    const float* W_rec2  = (const float*)d_in[5];
    const float* W_out   = (const float*)d_in[6];
    const float* alpha1  = (const float*)d_in[7];
    const float* rho1    = (const float*)d_in[8];
    const float* beta_a1 = (const float*)d_in[9];
    const float* alpha2  = (const float*)d_in[10];
    const float* rho2    = (const float*)d_in[11];
    const float* beta_a2 = (const float*)d_in[12];
    const float* beta_out= (const float*)d_in[13];
    float* out = (float*)d_out;

    static int smem_set = 0;
    if (!smem_set) {
        cudaFuncSetAttribute(k_gemm, cudaFuncAttributeMaxDynamicSharedMemorySize, GEMM_SMEM);
        smem_set = 1;
    }

    k_prep_build<<<PB_TOTAL, 1024>>>(x, delays, W_in, W_rec1, W2, W_rec2, W_out,
                                     alpha1, rho1, beta_a1, alpha2, rho2, beta_a2);

    {
        dim3 grid(H1 / BN, BT / BM);   // (8, 500)
        k_gemm<<<grid, 256, GEMM_SMEM>>>();
    }

    k_scan_fast<<<BATCH / 4, 128>>>(alpha1, rho1, beta_a1, alpha2, rho2, beta_a2, beta_out, out);
    k_scan<<<BATCH, 128>>>(alpha1, rho1, beta_a1, alpha2, rho2, beta_a2, beta_out, out);
}

// round 14
// speedup vs baseline: 1.1287x; 1.0019x over previous
#include <cuda_runtime.h>
#include <cuda_bf16.h>
#include <stdint.h>

// ---------------- problem constants (fixed shapes) ----------------
#define BATCH 256
#define TT    250
#define CC    700
#define KP    704          // C padded (int8 bytes per row; 44*16)
#define KP16  352          // row length in uint16 units
#define H1    1024
#define H2    512
#define OO    20
#define BT    (BATCH*TT)   // 64000

// ---------------- device scratch ----------------
static __device__ uint8_t g_xd8[(size_t)BT * KP];         // delayed input {0,1} int8, 45MB
static __device__ int8_t  g_Wq[H1 * KP];                  // quantized W_in [h][c]
static __device__ float   g_qscale[H1];                   // per-row scales
static __device__ __nv_bfloat16 g_IinB[(size_t)BT * H1];  // I_in bf16 [r][h], 131MB
static __device__ float g_Wr1T[H1 * H1];                  // [j][h]
static __device__ float g_W2T[H1 * H2];                   // [j1][h2]
static __device__ float g_Wr2T[H2 * H2];                  // [j2][h2]
static __device__ float g_WoT[H2 * OO];                   // [j2][o]
static __device__ int   g_uniflag;                        // 1 if neuron params uniform

#define CP_ASYNC16(dst_u32, src_ptr) \
    asm volatile("cp.async.cg.shared.global [%0], [%1], 16;\n" :: "r"(dst_u32), "l"(src_ptr))
#define CP_COMMIT() asm volatile("cp.async.commit_group;\n" ::)

// ---------------- K1: fused prep (R13-proven) ----------------
#define PB_TOTAL 2082

__global__ void __launch_bounds__(1024) k_prep_build(
    const float* __restrict__ x, const int* __restrict__ delays,
    const float* __restrict__ Win, const float* __restrict__ Wr1,
    const float* __restrict__ W2, const float* __restrict__ Wr2,
    const float* __restrict__ Wo,
    const float* __restrict__ Al1, const float* __restrict__ Rh1, const float* __restrict__ Ba1,
    const float* __restrict__ Al2, const float* __restrict__ Rh2, const float* __restrict__ Ba2)
{
    __shared__ uint8_t stage8[TT * 128];   // 32000 B
    __shared__ int dsh[KP];
    __shared__ float tile[32][33];
    __shared__ int okflag;

    const int blk = blockIdx.x;
    const int tid = threadIdx.x;
    const int tx = tid & 31, ty = tid >> 5;

    if (blk < 256) {
        const int b = blk;
        for (int i = tid; i < KP; i += 1024) dsh[i] = (i < CC) ? delays[i] : 0;

        const float* xb = x + (size_t)b * TT * CC;
        uint32_t* outw = reinterpret_cast<uint32_t*>(g_xd8) + (size_t)b * TT * (KP / 4);

        for (int c0 = 0; c0 < KP; c0 += 128) {
            const int w = (c0 + 128 <= CC) ? 128 : (CC > c0 ? CC - c0 : 0);   // 128 or 60
            __syncthreads();
            for (int idx = tid; idx < TT * 32; idx += 1024) {
                const int t = idx >> 5, c4 = idx & 31;
                uint32_t word = 0;
                if (c4 * 4 < w) {
                    const float4 v = *(const float4*)&xb[(size_t)t * CC + c0 + c4 * 4];
                    word  = (uint32_t)(v.x != 0.0f);
                    word |= (uint32_t)(v.y != 0.0f) << 8;
                    word |= (uint32_t)(v.z != 0.0f) << 16;
                    word |= (uint32_t)(v.w != 0.0f) << 24;
                }
                *reinterpret_cast<uint32_t*>(&stage8[t * 128 + c4 * 4]) = word;
            }
            __syncthreads();
            for (int idx = tid; idx < TT * 32; idx += 1024) {
                const int t = idx >> 5, w4 = idx & 31;
                uint32_t word = 0;
#pragma unroll
                for (int j = 0; j < 4; ++j) {
                    const int c = c0 + w4 * 4 + j;
                    const int ttt = t - dsh[c];
                    uint8_t byte = 0;
                    if (ttt >= 0 && (w4 * 4 + j) < w) byte = stage8[ttt * 128 + w4 * 4 + j];
                    word |= (uint32_t)byte << (8 * j);
                }
                outw[(size_t)t * (KP / 4) + (c0 >> 2) + w4] = word;
            }
        }
    } else if (blk < 288) {
        const int row = (blk - 256) * 32 + ty;
        float m = 0.0f;
        for (int c = tx; c < CC; c += 32) m = fmaxf(m, fabsf(Win[row * CC + c]));
#pragma unroll
        for (int off = 16; off; off >>= 1) m = fmaxf(m, __shfl_xor_sync(0xFFFFFFFFu, m, off));
        const float inv = (m > 0.0f) ? 127.0f / m : 0.0f;
        if (tx == 0) g_qscale[row] = m * (1.0f / 127.0f);
        for (int c = tx; c < KP; c += 32) {
            float wv = (c < CC) ? Win[row * CC + c] : 0.0f;
            g_Wq[row * KP + c] = (int8_t)__float2int_rn(wv * inv);
        }
    } else if (blk < 1312) {
        const int tI = blk - 288;
        const int tr = tI >> 5, tc = tI & 31;
        tile[ty][tx] = Wr1[(tr * 32 + ty) * H1 + tc * 32 + tx];
        __syncthreads();
        g_Wr1T[(tc * 32 + ty) * H1 + tr * 32 + tx] = tile[tx][ty];
    } else if (blk < 1824) {
        const int tI = blk - 1312;
        const int th = tI & 15, tj = tI >> 4;
        tile[ty][tx] = W2[(th * 32 + ty) * H1 + tj * 32 + tx];
        __syncthreads();
        g_W2T[(tj * 32 + ty) * H2 + th * 32 + tx] = tile[tx][ty];
    } else if (blk < 2080) {
        const int tI = blk - 1824;
        const int tr = tI >> 4, tc = tI & 15;
        tile[ty][tx] = Wr2[(tr * 32 + ty) * H2 + tc * 32 + tx];
        __syncthreads();
        g_Wr2T[(tc * 32 + ty) * H2 + tr * 32 + tx] = tile[tx][ty];
    } else if (blk == 2080) {
        for (int i = tid; i < H2 * OO; i += 1024) {
            int j = i / OO, o = i % OO;
            g_WoT[i] = Wo[o * H2 + j];
        }
    } else {
        if (tid == 0) okflag = 1;
        __syncthreads();
        const float a10 = Al1[0], r10 = Rh1[0], b10 = Ba1[0];
        const float a20 = Al2[0], r20 = Rh2[0], b20 = Ba2[0];
        int good = 1;
        for (int i = tid; i < H1; i += 1024)
            if (Al1[i] != a10 || Rh1[i] != r10 || Ba1[i] != b10) good = 0;
        for (int i = tid; i < H2; i += 1024)
            if (Al2[i] != a20 || Rh2[i] != r20 || Ba2[i] != b20) good = 0;
        if (!good) atomicAnd(&okflag, 0);
        __syncthreads();
        if (tid == 0) g_uniflag = okflag;
    }
}

// ---------------- K3: int8 IMMA GEMM, 4-stage cp.async (R9-proven) ----------------
#define BM 128
#define BN 128
#define BKK 32      // uint16 units per K-tile (= 64 int8)
#define SMSTR 40    // uint16 row stride (80B)
#define NSTG 4
#define GEMM_SMEM (NSTG * (BM + BN) * SMSTR * 2)   // 81920 bytes

#define CP_WAIT2()  asm volatile("cp.async.wait_group 2;\n" ::: "memory")

__global__ void __launch_bounds__(256, 2) k_gemm()
{
    extern __shared__ uint16_t smem[];
    uint16_t* Abase = smem;
    uint16_t* Bbase = smem + NSTG * BM * SMSTR;

    const int tid    = threadIdx.x;
    const int warpId = tid >> 5;
    const int lane   = tid & 31;
    const int g      = lane >> 2;
    const int t4     = lane & 3;

    const int row0 = blockIdx.y * BM;
    const int col0 = blockIdx.x * BN;
    const int wm   = (warpId & 1) * 64;
    const int wn   = (warpId >> 1) * 32;

    const int lrow0 = tid >> 2;
    const int lseg  = (tid & 3) * 8;

    const uint16_t* Ag = reinterpret_cast<const uint16_t*>(g_xd8) + (size_t)row0 * KP16;
    const uint16_t* Bg = reinterpret_cast<const uint16_t*>(g_Wq)  + (size_t)col0 * KP16;

    uint32_t sA[NSTG], sB[NSTG];
#pragma unroll
    for (int s = 0; s < NSTG; ++s) {
        sA[s] = (uint32_t)__cvta_generic_to_shared(Abase + s * BM * SMSTR);
        sB[s] = (uint32_t)__cvta_generic_to_shared(Bbase + s * BN * SMSTR);
    }

    const int aoff = ((wm + (lane & 15)) * SMSTR + (lane >> 4) * 8) * 2;
    const int boff = ((wn + (lane & 7) + ((lane >> 4) << 3)) * SMSTR + ((lane >> 3) & 1) * 8) * 2;

    int acc[4][4][4];
#pragma unroll
    for (int i = 0; i < 4; ++i)
#pragma unroll
        for (int j = 0; j < 4; ++j)
#pragma unroll
            for (int c = 0; c < 4; ++c) acc[i][j][c] = 0;

    const int NK = KP16 / BKK;   // 11

#pragma unroll
    for (int s = 0; s < 3; ++s) {
        const int k0 = s * BKK;
        CP_ASYNC16(sA[s] + (lrow0 * SMSTR + lseg) * 2,        Ag + (size_t)lrow0 * KP16 + k0 + lseg);
        CP_ASYNC16(sA[s] + ((lrow0 + 64) * SMSTR + lseg) * 2, Ag + (size_t)(lrow0 + 64) * KP16 + k0 + lseg);
        CP_ASYNC16(sB[s] + (lrow0 * SMSTR + lseg) * 2,        Bg + (size_t)lrow0 * KP16 + k0 + lseg);
        CP_ASYNC16(sB[s] + ((lrow0 + 64) * SMSTR + lseg) * 2, Bg + (size_t)(lrow0 + 64) * KP16 + k0 + lseg);
        CP_COMMIT();
    }

    for (int kt = 0; kt < NK; ++kt) {
        const int st = kt & 3;
        CP_WAIT2();
        __syncthreads();

        if (kt + 3 < NK) {
            const int s = (kt + 3) & 3;
            const int k0 = (kt + 3) * BKK;
            CP_ASYNC16(sA[s] + (lrow0 * SMSTR + lseg) * 2,        Ag + (size_t)lrow0 * KP16 + k0 + lseg);
            CP_ASYNC16(sA[s] + ((lrow0 + 64) * SMSTR + lseg) * 2, Ag + (size_t)(lrow0 + 64) * KP16 + k0 + lseg);
            CP_ASYNC16(sB[s] + (lrow0 * SMSTR + lseg) * 2,        Bg + (size_t)lrow0 * KP16 + k0 + lseg);
            CP_ASYNC16(sB[s] + ((lrow0 + 64) * SMSTR + lseg) * 2, Bg + (size_t)(lrow0 + 64) * KP16 + k0 + lseg);
        }
        CP_COMMIT();

        const uint32_t aBase = sA[st] + aoff;
        const uint32_t bBase = sB[st] + boff;
#pragma unroll
        for (int ks = 0; ks < BKK; ks += 16) {
            uint32_t af[4][4];
            uint32_t bq[2][4];
#pragma unroll
            for (int i = 0; i < 4; ++i) {
                asm volatile("ldmatrix.sync.aligned.m8n8.x4.shared.b16 {%0,%1,%2,%3}, [%4];"
                             : "=r"(af[i][0]), "=r"(af[i][1]), "=r"(af[i][2]), "=r"(af[i][3])
                             : "r"(aBase + (i * 16 * SMSTR + ks) * 2));
            }
#pragma unroll
            for (int j2 = 0; j2 < 2; ++j2) {
                asm volatile("ldmatrix.sync.aligned.m8n8.x4.shared.b16 {%0,%1,%2,%3}, [%4];"
                             : "=r"(bq[j2][0]), "=r"(bq[j2][1]), "=r"(bq[j2][2]), "=r"(bq[j2][3])
                             : "r"(bBase + (j2 * 16 * SMSTR + ks) * 2));
            }
#pragma unroll
            for (int i = 0; i < 4; ++i)
#pragma unroll
                for (int j = 0; j < 4; ++j) {
                    const uint32_t b0 = bq[j >> 1][(j & 1) * 2];
                    const uint32_t b1 = bq[j >> 1][(j & 1) * 2 + 1];
                    asm volatile(
                        "mma.sync.aligned.m16n8k32.row.col.s32.s8.s8.s32 "
                        "{%0,%1,%2,%3}, {%4,%5,%6,%7}, {%8,%9}, {%0,%1,%2,%3};\n"
                        : "+r"(acc[i][j][0]), "+r"(acc[i][j][1]),
                          "+r"(acc[i][j][2]), "+r"(acc[i][j][3])
                        : "r"(af[i][0]), "r"(af[i][1]), "r"(af[i][2]), "r"(af[i][3]),
                          "r"(b0), "r"(b1));
                }
        }
    }

#pragma unroll
    for (int j = 0; j < 4; ++j) {
        const int c = col0 + wn + j * 8 + 2 * t4;
        const float sc0 = g_qscale[c];
        const float sc1 = g_qscale[c + 1];
#pragma unroll
        for (int i = 0; i < 4; ++i) {
            const int r0 = row0 + wm + i * 16 + g;
            __nv_bfloat162 p0 = __float22bfloat162_rn(
                make_float2(sc0 * (float)acc[i][j][0], sc1 * (float)acc[i][j][1]));
            __nv_bfloat162 p1 = __float22bfloat162_rn(
                make_float2(sc0 * (float)acc[i][j][2], sc1 * (float)acc[i][j][3]));
            *reinterpret_cast<__nv_bfloat162*>(&g_IinB[(size_t)r0 * H1 + c])       = p0;
            *reinterpret_cast<__nv_bfloat162*>(&g_IinB[(size_t)(r0 + 8) * H1 + c]) = p1;
        }
    }
}

// ---------------- K4a: FAST scan — 2 warps per batch, 1 cheap barrier/step ----------------
// Warp w owns L1 neurons [512w, 512w+512) (lane: 512w+16l+j, j<16, mask bit j)
// and L2 neurons [256w, 256w+256) (lane: 256w+8l+j, j<8, mask bit j).
// Cross-warp spike exchange via parity-double-buffered smem flags/masks.
__global__ void __launch_bounds__(64) k_scan_fast(
    const float* __restrict__ alpha1, const float* __restrict__ rho1, const float* __restrict__ beta_a1,
    const float* __restrict__ alpha2, const float* __restrict__ rho2, const float* __restrict__ beta_a2,
    const float* __restrict__ beta_out, float* __restrict__ out)
{
    if (!g_uniflag) return;

    __shared__ uint4 ring[4][128];              // 8KB: 4 slots x 2048B rows
    __shared__ int      fl1[2][2], fl2[2][2];   // [parity][warp]
    __shared__ uint32_t msk1[2][2][32];         // [parity][warp][lane]
    __shared__ uint32_t msk2[2][2][32];

    const int w    = threadIdx.x >> 5;
    const int lane = threadIdx.x & 31;
    const int b    = blockIdx.x;

    const float al1 = alpha1[0], om1 = 1.0f - al1, rh1 = rho1[0], bA1 = beta_a1[0];
    const float al2 = alpha2[0], om2 = 1.0f - al2, rh2 = rho2[0], bA2 = beta_a2[0];
    float bo = 0.f, obo = 0.f;
    if (w == 0 && lane < OO) { bo = beta_out[lane]; obo = 1.0f - bo; }

    float v1[16], a1[16], v2[8], a2[8];
#pragma unroll
    for (int n = 0; n < 16; ++n) { v1[n] = 0.f; a1[n] = 0.f; }
#pragma unroll
    for (int n = 0; n < 8; ++n)  { v2[n] = 0.f; a2[n] = 0.f; }
    uint32_t m1 = 0, m2 = 0;      // own spike masks (16 / 8 bits)
    bool fA1 = false, fA2 = false;
    float vo = 0.f, vos = 0.f;

    if (threadIdx.x < 4) {
        fl1[threadIdx.x >> 1][threadIdx.x & 1] = 0;
        fl2[threadIdx.x >> 1][threadIdx.x & 1] = 0;
    }
    __syncthreads();

    const uint4* Ibg = reinterpret_cast<const uint4*>(g_IinB + (size_t)b * TT * H1);
    const int baseIdx = 64 * w + 2 * lane;      // uint4 index of this lane's 32B
    const uint32_t rAddr = (uint32_t)__cvta_generic_to_shared(&ring[0][baseIdx]);

#pragma unroll
    for (int s = 0; s < 3; ++s) {
        CP_ASYNC16(rAddr + s * 2048,      Ibg + (size_t)s * 128 + baseIdx);
        CP_ASYNC16(rAddr + s * 2048 + 16, Ibg + (size_t)s * 128 + baseIdx + 1);
        CP_COMMIT();
    }

    for (int t = 0; t < TT; ++t) {
        const int pt = t & 1, pp = pt ^ 1;
        asm volatile("cp.async.wait_group 2;\n" ::: "memory");
        const int sl = t & 3;
        const uint4 c0 = ring[sl][baseIdx];
        const uint4 c1 = ring[sl][baseIdx + 1];
        {
            const int tn = t + 3;
            if (tn < TT) {
                CP_ASYNC16(rAddr + (tn & 3) * 2048,      Ibg + (size_t)tn * 128 + baseIdx);
                CP_ASYNC16(rAddr + (tn & 3) * 2048 + 16, Ibg + (size_t)tn * 128 + baseIdx + 1);
            }
            CP_COMMIT();
        }

        float I1[16];
        {
            const uint32_t wd[8] = {c0.x, c0.y, c0.z, c0.w, c1.x, c1.y, c1.z, c1.w};
#pragma unroll
            for (int q = 0; q < 8; ++q) {
                const float2 f = __bfloat1622float2(
                    *reinterpret_cast<const __nv_bfloat162*>(&wd[q]));
                I1[2 * q]     = f.x;
                I1[2 * q + 1] = f.y;
            }
        }

        // ---- recurrent L1 input from step t-1 spikes (both warps, parity pp)
        const int fprev1 = fl1[pp][0] | fl1[pp][1];
        if (fprev1) {
#pragma unroll
            for (int ww = 0; ww < 2; ++ww) {
                if (!fl1[pp][ww]) continue;
                for (int sl2 = 0; sl2 < 32; ++sl2) {
                    uint32_t mm = msk1[pp][ww][sl2];
                    while (mm) {
                        const int k = __ffs(mm) - 1; mm &= mm - 1;
                        const int n = 512 * ww + 16 * sl2 + k;
                        const float* wr = &g_Wr1T[(size_t)n * H1 + 512 * w + 16 * lane];
#pragma unroll
                        for (int q = 0; q < 4; ++q) {
                            const float4 wv = *(const float4*)&wr[4 * q];
                            I1[4*q+0] += wv.x; I1[4*q+1] += wv.y;
                            I1[4*q+2] += wv.z; I1[4*q+3] += wv.w;
                        }
                    }
                }
            }
        }

        // ---- layer-1 membrane update
        if (!fprev1 && !fA1) {
#pragma unroll
            for (int n = 0; n < 16; ++n) v1[n] = fmaf(al1, v1[n], om1 * I1[n]);
        } else {
#pragma unroll
            for (int n = 0; n < 16; ++n) {
                const float s = (float)((m1 >> n) & 1u);
                v1[n] = fmaf(al1, v1[n], om1 * I1[n]) - s - a1[n];
            }
        }
        float mx = v1[0];
#pragma unroll
        for (int n = 1; n < 16; ++n) mx = fmaxf(mx, v1[n]);
        uint32_t nm1 = 0;
        if (__any_sync(0xFFFFFFFFu, mx >= 1.0f)) {
#pragma unroll
            for (int n = 0; n < 16; ++n) {
                const bool sp = (v1[n] >= 1.0f);
                nm1 |= ((uint32_t)sp) << n;
                a1[n] = rh1 * a1[n] + (sp ? bA1 : 0.0f);
            }
            fA1 = true;
            msk1[pt][w][lane] = nm1;
            if (lane == 0) fl1[pt][w] = 1;
        } else {
            if (fA1) {
#pragma unroll
                for (int n = 0; n < 16; ++n) a1[n] = rh1 * a1[n];
            }
            if (lane == 0) fl1[pt][w] = 0;
        }

        __syncthreads();   // the one barrier: publishes fl1/msk1[pt]; fences parity reuse

        // ---- layer-2 input: this-step L1 spikes + prev-step L2 spikes
        float I2[8];
#pragma unroll
        for (int n = 0; n < 8; ++n) I2[n] = 0.f;
        const int fnow1 = fl1[pt][0] | fl1[pt][1];
        if (fnow1) {
#pragma unroll
            for (int ww = 0; ww < 2; ++ww) {
                if (!fl1[pt][ww]) continue;
                for (int sl2 = 0; sl2 < 32; ++sl2) {
                    uint32_t mm = msk1[pt][ww][sl2];
                    while (mm) {
                        const int k = __ffs(mm) - 1; mm &= mm - 1;
                        const int n = 512 * ww + 16 * sl2 + k;
                        const float* wr = &g_W2T[(size_t)n * H2 + 256 * w + 8 * lane];
#pragma unroll
                        for (int q = 0; q < 2; ++q) {
                            const float4 wv = *(const float4*)&wr[4 * q];
                            I2[4*q+0] += wv.x; I2[4*q+1] += wv.y;
                            I2[4*q+2] += wv.z; I2[4*q+3] += wv.w;
                        }
                    }
                }
            }
        }
        const int fprev2 = fl2[pp][0] | fl2[pp][1];
        if (fprev2) {
#pragma unroll
            for (int ww = 0; ww < 2; ++ww) {
                if (!fl2[pp][ww]) continue;
                for (int sl2 = 0; sl2 < 32; ++sl2) {
                    uint32_t mm = msk2[pp][ww][sl2];
                    while (mm) {
                        const int k = __ffs(mm) - 1; mm &= mm - 1;
                        const int n = 256 * ww + 8 * sl2 + k;
                        const float* wr = &g_Wr2T[(size_t)n * H2 + 256 * w + 8 * lane];
#pragma unroll
                        for (int q = 0; q < 2; ++q) {
                            const float4 wv = *(const float4*)&wr[4 * q];
                            I2[4*q+0] += wv.x; I2[4*q+1] += wv.y;
                            I2[4*q+2] += wv.z; I2[4*q+3] += wv.w;
                        }
                    }
                }
            }
        }

        // ---- layer-2 membrane update
        if (!fnow1 && !fprev2 && !fA2) {
#pragma unroll
            for (int n = 0; n < 8; ++n) v2[n] = al2 * v2[n];
        } else {
#pragma unroll
            for (int n = 0; n < 8; ++n) {
                const float s = (float)((m2 >> n) & 1u);
                v2[n] = fmaf(al2, v2[n], om2 * I2[n]) - s - a2[n];
            }
        }
        float mx2 = v2[0];
#pragma unroll
        for (int n = 1; n < 8; ++n) mx2 = fmaxf(mx2, v2[n]);
        uint32_t nm2 = 0;
        if (__any_sync(0xFFFFFFFFu, mx2 >= 1.0f)) {
#pragma unroll
            for (int n = 0; n < 8; ++n) {
                const bool sp = (v2[n] >= 1.0f);
                nm2 |= ((uint32_t)sp) << n;
                a2[n] = rh2 * a2[n] + (sp ? bA2 : 0.0f);
            }
            fA2 = true;
            msk2[pt][w][lane] = nm2;
            if (lane == 0) fl2[pt][w] = 1;
        } else {
            if (fA2) {
#pragma unroll
                for (int n = 0; n < 8; ++n) a2[n] = rh2 * a2[n];
            }
            if (lane == 0) fl2[pt][w] = 0;
        }

        // ---- deferred readout for step t-1 (reads fl2/msk2[pp], stable through this step)
        if (w == 0 && lane < OO && t > 0) {
            float Io = 0.f;
            if (fprev2) {
#pragma unroll
                for (int ww = 0; ww < 2; ++ww) {
                    if (!fl2[pp][ww]) continue;
                    for (int sl2 = 0; sl2 < 32; ++sl2) {
                        uint32_t mm = msk2[pp][ww][sl2];
                        while (mm) {
                            const int k = __ffs(mm) - 1; mm &= mm - 1;
                            const int n = 256 * ww + 8 * sl2 + k;
                            Io += g_WoT[n * OO + lane];
                        }
                    }
                }
            }
            vo = bo * vo + obo * Io;
            vos += vo;
        }

        m1 = nm1; m2 = nm2;
    }

    __syncthreads();   // final step's fl2/msk2 (parity of t=249 -> 1) visible
    if (w == 0 && lane < OO) {
        float Io = 0.f;
        const int fp = 249 & 1;
        if (fl2[fp][0] | fl2[fp][1]) {
#pragma unroll
            for (int ww = 0; ww < 2; ++ww) {
                if (!fl2[fp][ww]) continue;
                for (int sl2 = 0; sl2 < 32; ++sl2) {
                    uint32_t mm = msk2[fp][ww][sl2];
                    while (mm) {
                        const int k = __ffs(mm) - 1; mm &= mm - 1;
                        const int n = 256 * ww + 8 * sl2 + k;
                        Io += g_WoT[n * OO + lane];
                    }
                }
            }
        }
        vo = bo * vo + obo * Io;
        vos += vo;
        out[b * OO + lane] = vos * (1.0f / (float)TT);
    }
}

// ---------------- K4b: GENERAL fallback scan (R12-proven; runs only if non-uniform) ----
#define RSLOTS 8
#define RDEPTH 7

__global__ void __launch_bounds__(128) k_scan(
    const float* __restrict__ alpha1, const float* __restrict__ rho1, const float* __restrict__ beta_a1,
    const float* __restrict__ alpha2, const float* __restrict__ rho2, const float* __restrict__ beta_a2,
    const float* __restrict__ beta_out, float* __restrict__ out)
{
    if (g_uniflag) return;

    __shared__ int cnt1[4], cnt2[4];
    __shared__ int act1[4][H1];
    __shared__ int act2[4][H2];
    __shared__ uint4 ring[RSLOTS][128];

    const int b   = blockIdx.x;
    const int tid = threadIdx.x;
    const int h0  = 8 * tid;
    const int h2  = 4 * tid;

    float alc1[8], rc1[8], bac1[8], v1[8], a1[8], s1[8];
#pragma unroll
    for (int k = 0; k < 2; ++k) {
        const float4 a = *(const float4*)&alpha1[h0 + 4 * k];
        const float4 r = *(const float4*)&rho1[h0 + 4 * k];
        const float4 bb = *(const float4*)&beta_a1[h0 + 4 * k];
        alc1[4*k] = a.x; alc1[4*k+1] = a.y; alc1[4*k+2] = a.z; alc1[4*k+3] = a.w;
        rc1[4*k] = r.x; rc1[4*k+1] = r.y; rc1[4*k+2] = r.z; rc1[4*k+3] = r.w;
        bac1[4*k] = bb.x; bac1[4*k+1] = bb.y; bac1[4*k+2] = bb.z; bac1[4*k+3] = bb.w;
    }
#pragma unroll
    for (int c = 0; c < 8; ++c) { v1[c] = 0.f; a1[c] = 0.f; s1[c] = 0.f; }

    float alc2[4], rc2[4], bac2[4], v2[4], a2[4], s2[4];
    {
        const float4 a = *(const float4*)&alpha2[h2];
        const float4 r = *(const float4*)&rho2[h2];
        const float4 bb = *(const float4*)&beta_a2[h2];
        alc2[0] = a.x; alc2[1] = a.y; alc2[2] = a.z; alc2[3] = a.w;
        rc2[0] = r.x; rc2[1] = r.y; rc2[2] = r.z; rc2[3] = r.w;
        bac2[0] = bb.x; bac2[1] = bb.y; bac2[2] = bb.z; bac2[3] = bb.w;
    }
#pragma unroll
    for (int c = 0; c < 4; ++c) { v2[c] = 0.f; a2[c] = 0.f; s2[c] = 0.f; }

    float bo = 0.f, obo = 0.f, vo = 0.f, vos = 0.f;
    if (tid < OO) { bo = beta_out[tid]; obo = 1.0f - bo; }

    if (tid == 0) {
#pragma unroll
        for (int s = 0; s < 4; ++s) { cnt1[s] = 0; cnt2[s] = 0; }
    }
    __syncthreads();

    const uint4* Ibg = reinterpret_cast<const uint4*>(g_IinB + (size_t)b * TT * H1) + tid;
    const uint32_t ringAddr = (uint32_t)__cvta_generic_to_shared(&ring[0][tid]);

#pragma unroll
    for (int s = 0; s < RDEPTH; ++s) {
        CP_ASYNC16(ringAddr + s * (128 * 16), Ibg + (size_t)s * (H1 / 8));
        CP_COMMIT();
    }

    for (int t = 0; t < TT; ++t) {
        asm volatile("cp.async.wait_group 6;\n" ::: "memory");
        const uint4 packed = ring[t & (RSLOTS - 1)][tid];
        {
            const int tn = t + RDEPTH;
            if (tn < TT)
                CP_ASYNC16(ringAddr + (tn & (RSLOTS - 1)) * (128 * 16), Ibg + (size_t)tn * (H1 / 8));
            CP_COMMIT();
        }

        const int sc = t & 3;
        const int sp = (t + 3) & 3;

        float I1[8];
        {
            const uint32_t pw[4] = {packed.x, packed.y, packed.z, packed.w};
#pragma unroll
            for (int k = 0; k < 4; ++k) {
                const __nv_bfloat162 bp = *reinterpret_cast<const __nv_bfloat162*>(&pw[k]);
                I1[2*k]   = __low2float(bp);
                I1[2*k+1] = __high2float(bp);
            }
        }
        const int n1 = cnt1[sp];
        for (int i = 0; i < n1; ++i) {
            const float* wr = &g_Wr1T[act1[sp][i] * H1 + h0];
            const float4 w0 = *(const float4*)wr;
            const float4 w1 = *(const float4*)(wr + 4);
            I1[0] += w0.x; I1[1] += w0.y; I1[2] += w0.z; I1[3] += w0.w;
            I1[4] += w1.x; I1[5] += w1.y; I1[6] += w1.z; I1[7] += w1.w;
        }
        float ns1[8];
#pragma unroll
        for (int c = 0; c < 8; ++c) {
            v1[c] = alc1[c] * v1[c] + (1.0f - alc1[c]) * I1[c] - s1[c] - a1[c];
            ns1[c] = (v1[c] >= 1.0f) ? 1.0f : 0.0f;
            a1[c] = rc1[c] * a1[c] + bac1[c] * ns1[c];
            s1[c] = ns1[c];
        }
#pragma unroll
        for (int c = 0; c < 8; ++c)
            if (ns1[c] != 0.0f) { int idx = atomicAdd(&cnt1[sc], 1); act1[sc][idx] = h0 + c; }

        __syncthreads();

        {
            float I2[4] = {0.f, 0.f, 0.f, 0.f};
            const int m1c = cnt1[sc];
            for (int i = 0; i < m1c; ++i) {
                const float4 wv = *(const float4*)&g_W2T[act1[sc][i] * H2 + h2];
                I2[0] += wv.x; I2[1] += wv.y; I2[2] += wv.z; I2[3] += wv.w;
            }
            const int n2 = cnt2[sp];
            for (int i = 0; i < n2; ++i) {
                const float4 wv = *(const float4*)&g_Wr2T[act2[sp][i] * H2 + h2];
                I2[0] += wv.x; I2[1] += wv.y; I2[2] += wv.z; I2[3] += wv.w;
            }
            float ns2[4];
#pragma unroll
            for (int c = 0; c < 4; ++c) {
                v2[c] = alc2[c] * v2[c] + (1.0f - alc2[c]) * I2[c] - s2[c] - a2[c];
                ns2[c] = (v2[c] >= 1.0f) ? 1.0f : 0.0f;
                a2[c] = rc2[c] * a2[c] + bac2[c] * ns2[c];
                s2[c] = ns2[c];
            }
#pragma unroll
            for (int c = 0; c < 4; ++c)
                if (ns2[c] != 0.0f) { int idx = atomicAdd(&cnt2[sc], 1); act2[sc][idx] = h2 + c; }
        }
        if (tid == 0) cnt1[(t + 2) & 3] = 0;
        if (tid == 1) cnt2[(t + 2) & 3] = 0;

        if (tid < OO && t > 0) {
            float Io = 0.f;
            const int m2c = cnt2[sp];
            for (int i = 0; i < m2c; ++i) Io += g_WoT[act2[sp][i] * OO + tid];
            vo = bo * vo + obo * Io;
            vos += vo;
        }
    }

    __syncthreads();
    if (tid < OO) {
        float Io = 0.f;
        const int m2c = cnt2[249 & 3];
        for (int i = 0; i < m2c; ++i) Io += g_WoT[act2[249 & 3][i] * OO + tid];
        vo = bo * vo + obo * Io;
        vos += vo;
        out[b * OO + tid] = vos * (1.0f / (float)TT);
    }
}

// ---------------- launch ----------------
extern "C" void kernel_launch(void* const* d_in, const int* in_sizes, int n_in,
                              void* d_out, int out_size)
{
    const float* x       = (const float*)d_in[0];
    const int*   delays  = (const int*)  d_in[1];
    const float* W_in    = (const float*)d_in[2];
    const float* W_rec1  = (const float*)d_in[3];
    const float* W2      = (const float*)d_in[4];
    const float* W_rec2  = (const float*)d_in[5];
    const float* W_out   = (const float*)d_in[6];
    const float* alpha1  = (const float*)d_in[7];
    const float* rho1    = (const float*)d_in[8];
    const float* beta_a1 = (const float*)d_in[9];
    const float* alpha2  = (const float*)d_in[10];
    const float* rho2    = (const float*)d_in[11];
    const float* beta_a2 = (const float*)d_in[12];
    const float* beta_out= (const float*)d_in[13];
    float* out = (float*)d_out;

    static int smem_set = 0;
    if (!smem_set) {
        cudaFuncSetAttribute(k_gemm, cudaFuncAttributeMaxDynamicSharedMemorySize, GEMM_SMEM);
        smem_set = 1;
    }

    k_prep_build<<<PB_TOTAL, 1024>>>(x, delays, W_in, W_rec1, W2, W_rec2, W_out,
                                     alpha1, rho1, beta_a1, alpha2, rho2, beta_a2);

    {
        dim3 grid(H1 / BN, BT / BM);   // (8, 500)
        k_gemm<<<grid, 256, GEMM_SMEM>>>();
    }

    k_scan_fast<<<BATCH, 64>>>(alpha1, rho1, beta_a1, alpha2, rho2, beta_a2, beta_out, out);
    k_scan<<<BATCH, 128>>>(alpha1, rho1, beta_a1, alpha2, rho2, beta_a2, beta_out, out);
}